// round 2
// baseline (speedup 1.0000x reference)
#include <cuda_runtime.h>
#include <cstdint>

#define Bb 64
#define Nn 196
#define Hh 512
#define Ee 512
#define Aa 512
#define Vv 20000
#define Ll 20
#define Tt 19   // recurrent steps (L-1)

// ---------------- scratch (static device globals; no allocation allowed) ----
__device__ float g_enc_proj[Bb*Nn*Aa];      // [B,N,A] 25.7 MB
__device__ float g_h[Bb*Hh];
__device__ float g_c[Bb*Hh];
__device__ float g_dec[Bb*Aa];
__device__ float g_scores[Bb*Nn];
__device__ float g_context[Bb*Hh];
__device__ float g_gates_x[Tt*Bb*4*Hh];     // precomputed x-part of gates (+biases)
__device__ float g_gates[Bb*4*Hh];
__device__ float g_hall[Tt*Bb*Hh];          // all h_t, row r = t*64+b

__device__ __forceinline__ float tanh_fast(float x) {
    float y; asm("tanh.approx.f32 %0, %1;" : "=f"(y) : "f"(x)); return y;
}
__device__ __forceinline__ float sigmoid_fast(float x) {
    return 1.0f / (1.0f + __expf(-x));
}

// ---------------- big tiled NT GEMM: C[m,n] = sum_k A[m,k]*Bw[n,k] + bias ----
// BM=BN=64, BK=16, 256 threads, 4x4 per thread.
// caps != nullptr  -> A row m gathered as emb[captions[(m%64)*L + m/64]]
// storemode 0: C[m*N+n]; storemode 1: fc remap -> out[(b*L + t+1)*V + n], m=t*64+b
__global__ void gemm_tiled(const float* __restrict__ A,
                           const float* __restrict__ Bw, int ldb,
                           const float* __restrict__ bias,
                           const float* __restrict__ bias2,
                           float* __restrict__ C,
                           int N, int K,
                           const int* __restrict__ caps,
                           int storemode)
{
    __shared__ float As[16][64];
    __shared__ float Bs[16][64];
    const int tid = threadIdx.x;
    const int m0 = blockIdx.y * 64;
    const int n0 = blockIdx.x * 64;
    const int lr = tid >> 2;            // row within tile (0..63)
    const int lc = (tid & 3) << 2;      // k within tile (0,4,8,12)

    const int am = m0 + lr;             // M is always a multiple of 64 here
    const float* arow;
    if (caps) {
        int ci = caps[(am & 63) * Ll + (am >> 6)];
        ci = ci < 0 ? 0 : (ci >= Vv ? Vv - 1 : ci);   // defensive clamp
        arow = A + (size_t)ci * K + lc;
    } else {
        arow = A + (size_t)am * K + lc;
    }
    const int bn = n0 + lr;
    const bool bvalid = (bn < N);
    const float* brow = Bw + (size_t)(bvalid ? bn : 0) * ldb + lc;

    float acc[4][4];
#pragma unroll
    for (int i = 0; i < 4; i++)
#pragma unroll
        for (int j = 0; j < 4; j++) acc[i][j] = 0.0f;

    const int tx = tid & 15, ty = tid >> 4;

    for (int k0 = 0; k0 < K; k0 += 16) {
        float4 av = *(const float4*)(arow + k0);
        float4 bv = bvalid ? *(const float4*)(brow + k0) : make_float4(0.f,0.f,0.f,0.f);
        As[lc+0][lr] = av.x; As[lc+1][lr] = av.y; As[lc+2][lr] = av.z; As[lc+3][lr] = av.w;
        Bs[lc+0][lr] = bv.x; Bs[lc+1][lr] = bv.y; Bs[lc+2][lr] = bv.z; Bs[lc+3][lr] = bv.w;
        __syncthreads();
#pragma unroll
        for (int kk = 0; kk < 16; kk++) {
            float4 a4 = *(const float4*)&As[kk][ty << 2];
            float4 b4 = *(const float4*)&Bs[kk][tx << 2];
            float a_[4] = {a4.x, a4.y, a4.z, a4.w};
            float b_[4] = {b4.x, b4.y, b4.z, b4.w};
#pragma unroll
            for (int i = 0; i < 4; i++)
#pragma unroll
                for (int j = 0; j < 4; j++) acc[i][j] += a_[i] * b_[j];
        }
        __syncthreads();
    }

#pragma unroll
    for (int i = 0; i < 4; i++) {
        const int m = m0 + (ty << 2) + i;
#pragma unroll
        for (int j = 0; j < 4; j++) {
            const int n = n0 + (tx << 2) + j;
            if (n < N) {
                float v = acc[i][j];
                if (bias)  v += bias[n];
                if (bias2) v += bias2[n];
                if (storemode == 0) {
                    C[(size_t)m * N + n] = v;
                } else {
                    const int t = m >> 6, b = m & 63;
                    C[((size_t)b * Ll + t + 1) * Vv + n] = v;
                }
            }
        }
    }
}

// ---------------- small-M (M=64) GEMM: two K segments (context|h etc.) -------
// C[64,N] = bias + Cinit + sum_k A(k)*W(n,k); BN=16, BK=16, 256 threads.
__global__ void gemm_smallm(const float* __restrict__ A1, int K1,
                            const float* __restrict__ W1, int ldw1, int offw1,
                            const float* __restrict__ A2,
                            const float* __restrict__ W2, int ldw2, int K2,
                            const float* __restrict__ bias,
                            const float* __restrict__ Cinit,
                            float* __restrict__ C, int N)
{
    __shared__ float As[16][64];
    __shared__ float Bs[16][16];
    const int tid = threadIdx.x;
    const int n0 = blockIdx.x * 16;
    const int lr = tid >> 2;            // A row 0..63
    const int lc = (tid & 3) << 2;      // A k
    const int bn = tid & 15;            // W n
    const int bk = tid >> 4;            // W k 0..15
    const int tx = tid & 15;            // out n
    const int ty = tid >> 4;            // out m-group

    float acc[4] = {0.f, 0.f, 0.f, 0.f};
    const int K = K1 + K2;

    for (int k0 = 0; k0 < K; k0 += 16) {
        float4 av; float wv;
        if (k0 < K1) {
            av = *(const float4*)(A1 + lr * K1 + k0 + lc);
            wv = W1[(size_t)(n0 + bn) * ldw1 + offw1 + k0 + bk];
        } else {
            const int kq = k0 - K1;
            av = *(const float4*)(A2 + lr * K2 + kq + lc);
            wv = W2[(size_t)(n0 + bn) * ldw2 + kq + bk];
        }
        As[lc+0][lr] = av.x; As[lc+1][lr] = av.y; As[lc+2][lr] = av.z; As[lc+3][lr] = av.w;
        Bs[bk][bn] = wv;
        __syncthreads();
#pragma unroll
        for (int kk = 0; kk < 16; kk++) {
            float4 a4 = *(const float4*)&As[kk][ty << 2];
            float bb = Bs[kk][tx];
            acc[0] += a4.x * bb; acc[1] += a4.y * bb;
            acc[2] += a4.z * bb; acc[3] += a4.w * bb;
        }
        __syncthreads();
    }

    const int n = n0 + tx;
    const float badd = bias ? bias[n] : 0.0f;
#pragma unroll
    for (int i = 0; i < 4; i++) {
        const int m = (ty << 2) + i;
        float v = acc[i] + badd;
        if (Cinit) v += Cinit[(size_t)m * N + n];
        C[(size_t)m * N + n] = v;
    }
}

// ---------------- attention scores: warp per (b,n) ---------------------------
__global__ void scores_kernel(const float* __restrict__ eW,
                              const float* __restrict__ eb)
{
    const int w = blockIdx.x * 8 + (threadIdx.x >> 5);   // 0..12543
    const int lane = threadIdx.x & 31;
    const int b = w / Nn, n = w - b * Nn;
    const float* ep = g_enc_proj + ((size_t)b * Nn + n) * Aa;
    const float* dc = g_dec + b * Aa;
    float acc = 0.0f;
#pragma unroll 4
    for (int a = lane; a < Aa; a += 32)
        acc += tanh_fast(ep[a] + dc[a]) * eW[a];
#pragma unroll
    for (int o = 16; o; o >>= 1) acc += __shfl_xor_sync(0xffffffffu, acc, o);
    if (lane == 0) g_scores[b * Nn + n] = acc + eb[0];
}

// ---------------- softmax over N=196 + context = attw @ enc_out --------------
__global__ void softmax_ctx_kernel(const float* __restrict__ enc_out)
{
    __shared__ float sw[Nn];
    __shared__ float red[256];
    const int b = blockIdx.x, tid = threadIdx.x;
    float v = (tid < Nn) ? g_scores[b * Nn + tid] : -1e30f;
    red[tid] = v; __syncthreads();
    for (int s = 128; s; s >>= 1) { if (tid < s) red[tid] = fmaxf(red[tid], red[tid+s]); __syncthreads(); }
    const float mx = red[0]; __syncthreads();
    float e = (tid < Nn) ? __expf(v - mx) : 0.0f;
    red[tid] = e; __syncthreads();
    for (int s = 128; s; s >>= 1) { if (tid < s) red[tid] += red[tid+s]; __syncthreads(); }
    const float inv = 1.0f / red[0];
    if (tid < Nn) sw[tid] = e * inv;
    __syncthreads();

    const int h = blockIdx.y * 256 + tid;
    const float* eo = enc_out + (size_t)b * Nn * Hh + h;
    float acc = 0.0f;
#pragma unroll 7
    for (int n = 0; n < Nn; n++) acc += sw[n] * eo[(size_t)n * Hh];
    g_context[b * Hh + h] = acc;
}

// ---------------- LSTM pointwise cell update ----------------------------------
__global__ void cell_update(int t)
{
    const int b = blockIdx.x, u = threadIdx.x;
    const int idx = b * Hh + u;
    const float* g = g_gates + b * 4 * Hh;
    const float gi = g[u], gf = g[Hh + u], gg = g[2*Hh + u], go = g[3*Hh + u];
    const float cn = sigmoid_fast(gf) * g_c[idx] + sigmoid_fast(gi) * tanh_fast(gg);
    const float hn = sigmoid_fast(go) * tanh_fast(cn);
    g_c[idx] = cn;
    g_h[idx] = hn;
    g_hall[(size_t)t * Bb * Hh + idx] = hn;
}

// ---------------- init / output zeroing ---------------------------------------
__global__ void init_hc()
{
    const int i = blockIdx.x * blockDim.x + threadIdx.x;
    if (i < Bb * Hh) { g_h[i] = 0.0f; g_c[i] = 0.0f; }
}
__global__ void zero_out0(float* __restrict__ out)
{
    for (int i = blockIdx.x * blockDim.x + threadIdx.x; i < Bb * Vv;
         i += gridDim.x * blockDim.x) {
        const int b = i / Vv, v = i - b * Vv;
        out[(size_t)b * Ll * Vv + v] = 0.0f;
    }
}

// ---------------- launch ------------------------------------------------------
extern "C" void kernel_launch(void* const* d_in, const int* in_sizes, int n_in,
                              void* d_out, int out_size)
{
    const float* enc_out  = (const float*)d_in[0];
    const int*   captions = (const int*)d_in[1];     // JAX x64-disabled: int32
    const float* emb      = (const float*)d_in[2];
    const float* W_ih     = (const float*)d_in[3];
    const float* W_hh     = (const float*)d_in[4];
    const float* b_ih     = (const float*)d_in[5];
    const float* b_hh     = (const float*)d_in[6];
    const float* enc_W    = (const float*)d_in[7];
    const float* enc_b    = (const float*)d_in[8];
    const float* dec_W    = (const float*)d_in[9];
    const float* dec_b    = (const float*)d_in[10];
    const float* energy_W = (const float*)d_in[11];
    const float* energy_b = (const float*)d_in[12];
    const float* fc_W     = (const float*)d_in[13];
    const float* fc_b     = (const float*)d_in[14];
    float* out = (float*)d_out;

    float *p_enc_proj, *p_gates_x, *p_hall, *p_dec, *p_ctx, *p_h, *p_gates;
    cudaGetSymbolAddress((void**)&p_enc_proj, g_enc_proj);
    cudaGetSymbolAddress((void**)&p_gates_x,  g_gates_x);
    cudaGetSymbolAddress((void**)&p_hall,     g_hall);
    cudaGetSymbolAddress((void**)&p_dec,      g_dec);
    cudaGetSymbolAddress((void**)&p_ctx,      g_context);
    cudaGetSymbolAddress((void**)&p_h,        g_h);
    cudaGetSymbolAddress((void**)&p_gates,    g_gates);

    init_hc<<<(Bb*Hh + 255) / 256, 256>>>();
    zero_out0<<<256, 256>>>(out);

    // enc_proj = encoder_outputs @ enc_W^T + enc_b   [12544, 512] K=512
    {
        dim3 grid(512 / 64, (Bb * Nn) / 64);
        gemm_tiled<<<grid, 256>>>(enc_out, enc_W, 512, enc_b, nullptr,
                                  p_enc_proj, 512, 512, nullptr, 0);
    }
    // gates_x[t,b,:] = emb[cap[b,t]] @ W_ih[:, :512]^T + b_ih + b_hh   [1216, 2048]
    {
        dim3 grid(2048 / 64, (Tt * Bb) / 64);
        gemm_tiled<<<grid, 256>>>(emb, W_ih, 1024, b_ih, b_hh,
                                  p_gates_x, 2048, 512, captions, 0);
    }

    for (int t = 0; t < Tt; t++) {
        // dec = h @ dec_W^T + dec_b   [64, 512]
        gemm_smallm<<<512 / 16, 256>>>(p_h, 512, dec_W, 512, 0,
                                       nullptr, nullptr, 0, 0,
                                       dec_b, nullptr, p_dec, 512);
        // scores[b,n] = sum_a tanh(enc_proj + dec) * eW + eb
        scores_kernel<<<(Bb * Nn) / 8, 256>>>(energy_W, energy_b);
        // softmax + context
        softmax_ctx_kernel<<<dim3(Bb, 2), 256>>>(enc_out);
        // gates = gates_x[t] + ctx @ W_ih[:,512:1024]^T + h @ W_hh^T   [64, 2048]
        gemm_smallm<<<2048 / 16, 256>>>(p_ctx, 512, W_ih, 1024, 512,
                                        p_h, W_hh, 512, 512,
                                        nullptr, p_gates_x + (size_t)t * Bb * 4 * Hh,
                                        p_gates, 2048);
        // LSTM cell + record h_t
        cell_update<<<Bb, Hh>>>(t);
    }

    // out[b, t+1, :] = hall @ fc_W^T + fc_b   [1216, 20000] K=512
    {
        dim3 grid((Vv + 63) / 64, (Tt * Bb) / 64);
        gemm_tiled<<<grid, 256>>>(p_hall, fc_W, 512, fc_b, nullptr,
                                  out, Vv, 512, nullptr, 1);
    }
}

// round 3
// speedup vs baseline: 1.2245x; 1.2245x over previous
#include <cuda_runtime.h>
#include <cstdint>

#define Bb 64
#define Nn 196
#define Hh 512
#define Aa 512
#define Vv 20000
#define Ll 20
#define Tt 19

typedef unsigned long long ull;

// ---------------- scratch ----------------------------------------------------
__device__ float g_enc_proj[Bb*Nn*Aa];        // 25.7 MB
__device__ float g_h[Bb*Hh];
__device__ float g_c[Bb*Hh];
__device__ float g_context[Bb*Hh];
__device__ float g_gates_x[Tt*Bb*4*Hh];       // x-part of gates (+both biases)
__device__ float g_dec_part[4*Bb*Aa];         // split-K partials for dec
__device__ float g_gates_part[4*Bb*4*Hh];     // split-K partials for gates
__device__ float g_hall[1280*Hh];             // all h_t (padded to 1280 rows)

__device__ __forceinline__ float tanh_fast(float x) {
    float y; asm("tanh.approx.f32 %0, %1;" : "=f"(y) : "f"(x)); return y;
}
__device__ __forceinline__ float sigmoid_fast(float x) {
    return 1.0f / (1.0f + __expf(-x));
}

#define FFMA2(d, a, b) asm("fma.rn.f32x2 %0, %1, %2, %0;" : "+l"(d) : "l"(a), "l"(b))
#define PACK_DUP(d, s) asm("mov.b64 %0, {%1, %1};" : "=l"(d) : "f"(s))
#define UNPACK2(lo, hi, s) asm("mov.b64 {%0, %1}, %2;" : "=f"(lo), "=f"(hi) : "l"(s))

// ============ big GEMM: 128x128 tile, BK=8, 256 thr, 8x8/thread, f32x2 ======
// C[m,n] = sum_k A[m,k] * Bw[n,k] (+bias[n] +bias2[n])
// caps: row gather  A row = emb[captions[(m%64)*L + m/64]]
// storemode 0: C[m*N+n];  1: out[((m%64)*L + m/64 + 1)*V + n]
__global__ void gemm128(const float* __restrict__ A,
                        const float* __restrict__ Bw, int ldb,
                        const float* __restrict__ bias,
                        const float* __restrict__ bias2,
                        float* __restrict__ C,
                        int Mvalid, int N, int K,
                        const int* __restrict__ caps, int storemode)
{
    __shared__ ull   As2[8][128];   // A values duplicated into f32x2 pairs
    __shared__ float Bs[8][128];

    const int tid = threadIdx.x;
    const int m0 = blockIdx.y * 128;
    const int n0 = blockIdx.x * 128;

    // loader mapping: 256 threads -> 128 rows x 2 k-segments (4 floats each)
    const int lrow = tid >> 1;
    const int lk   = (tid & 1) << 2;

    int am = m0 + lrow;
    const float* arow;
    if (caps) {
        int mm = (am < Mvalid) ? am : 0;
        int ci = caps[(mm & 63) * Ll + (mm >> 6)];
        ci = ci < 0 ? 0 : (ci >= Vv ? Vv - 1 : ci);
        arow = A + (size_t)ci * K + lk;
    } else {
        int mm = (am < Mvalid) ? am : (Mvalid - 1);
        arow = A + (size_t)mm * K + lk;
    }
    const int bn = n0 + lrow;
    const bool bval = (bn < N);
    const float* brow = Bw + (size_t)(bval ? bn : 0) * ldb + lk;

    const int tx = tid & 15, ty = tid >> 4;

    ull acc[8][4];
#pragma unroll
    for (int i = 0; i < 8; i++)
#pragma unroll
        for (int j = 0; j < 4; j++) acc[i][j] = 0ULL;

    float4 av = *(const float4*)(arow);
    float4 bv = bval ? *(const float4*)(brow) : make_float4(0.f,0.f,0.f,0.f);

    for (int k0 = 0; k0 < K; k0 += 8) {
        // store current tile (A duplicated into pairs)
        ull d0, d1, d2, d3;
        PACK_DUP(d0, av.x); PACK_DUP(d1, av.y); PACK_DUP(d2, av.z); PACK_DUP(d3, av.w);
        As2[lk+0][lrow] = d0; As2[lk+1][lrow] = d1;
        As2[lk+2][lrow] = d2; As2[lk+3][lrow] = d3;
        Bs[lk+0][lrow] = bv.x; Bs[lk+1][lrow] = bv.y;
        Bs[lk+2][lrow] = bv.z; Bs[lk+3][lrow] = bv.w;
        __syncthreads();

        // prefetch next tile
        if (k0 + 8 < K) {
            av = *(const float4*)(arow + k0 + 8);
            bv = bval ? *(const float4*)(brow + k0 + 8) : make_float4(0.f,0.f,0.f,0.f);
        }

#pragma unroll
        for (int kk = 0; kk < 8; kk++) {
            const ull* ap = &As2[kk][ty << 3];
            const ulonglong2* bp = reinterpret_cast<const ulonglong2*>(&Bs[kk][tx << 3]);
            ulonglong2 q0 = bp[0], q1 = bp[1];
            ull b2[4] = {q0.x, q0.y, q1.x, q1.y};
#pragma unroll
            for (int i = 0; i < 8; i++) {
                ull a2 = ap[i];
                FFMA2(acc[i][0], a2, b2[0]);
                FFMA2(acc[i][1], a2, b2[1]);
                FFMA2(acc[i][2], a2, b2[2]);
                FFMA2(acc[i][3], a2, b2[3]);
            }
        }
        __syncthreads();
    }

#pragma unroll
    for (int i = 0; i < 8; i++) {
        const int m = m0 + (ty << 3) + i;
        if (m >= Mvalid) continue;
#pragma unroll
        for (int j = 0; j < 4; j++) {
            float lo, hi;
            UNPACK2(lo, hi, acc[i][j]);
            const int c0 = n0 + (tx << 3) + 2*j;
#pragma unroll
            for (int q = 0; q < 2; q++) {
                const int n = c0 + q;
                if (n >= N) continue;
                float v = (q ? hi : lo);
                if (bias)  v += bias[n];
                if (bias2) v += bias2[n];
                if (storemode == 0) {
                    C[(size_t)m * N + n] = v;
                } else {
                    const int t = m >> 6, b = m & 63;
                    C[((size_t)b * Ll + t + 1) * Vv + n] = v;
                }
            }
        }
    }
}

// ============ small-M (64) split-K GEMM -> partials =========================
// P[s][64][N] tile: block (ntile, s); K chunk = [s*KC, s*KC+KC)
// A is two K-segments: A1 (K1 cols) then A2 (512 cols)
__global__ void gemm64_split(const float* __restrict__ A1, int K1,
                             const float* __restrict__ W1, int ldw1, int offw1,
                             const float* __restrict__ A2,
                             const float* __restrict__ W2, int ldw2,
                             int KC, float* __restrict__ P, int N)
{
    __shared__ float As[16][64];
    __shared__ float Ws[16][64];
    const int tid = threadIdx.x;
    const int n0 = blockIdx.x * 64;
    const int s  = blockIdx.y;
    const int kbeg = s * KC, kend = kbeg + KC;

    const int row = tid >> 2;          // 0..63
    const int kc  = (tid & 3) << 2;    // 0,4,8,12
    const int tx = tid & 15, ty = tid >> 4;

    float acc[4][4];
#pragma unroll
    for (int i = 0; i < 4; i++)
#pragma unroll
        for (int j = 0; j < 4; j++) acc[i][j] = 0.0f;

    for (int k0 = kbeg; k0 < kend; k0 += 16) {
        float4 av, wv;
        if (k0 < K1) {
            av = *(const float4*)(A1 + (size_t)row * K1 + k0 + kc);
            wv = *(const float4*)(W1 + (size_t)(n0 + row) * ldw1 + offw1 + k0 + kc);
        } else {
            const int kq = k0 - K1;
            av = *(const float4*)(A2 + (size_t)row * 512 + kq + kc);
            wv = *(const float4*)(W2 + (size_t)(n0 + row) * ldw2 + kq + kc);
        }
        As[kc+0][row] = av.x; As[kc+1][row] = av.y; As[kc+2][row] = av.z; As[kc+3][row] = av.w;
        Ws[kc+0][row] = wv.x; Ws[kc+1][row] = wv.y; Ws[kc+2][row] = wv.z; Ws[kc+3][row] = wv.w;
        __syncthreads();
#pragma unroll
        for (int kk = 0; kk < 16; kk++) {
            float4 a4 = *(const float4*)&As[kk][ty << 2];
            float4 w4 = *(const float4*)&Ws[kk][tx << 2];
            float a_[4] = {a4.x, a4.y, a4.z, a4.w};
            float w_[4] = {w4.x, w4.y, w4.z, w4.w};
#pragma unroll
            for (int i = 0; i < 4; i++)
#pragma unroll
                for (int j = 0; j < 4; j++) acc[i][j] += a_[i] * w_[j];
        }
        __syncthreads();
    }

#pragma unroll
    for (int i = 0; i < 4; i++) {
        const int m = (ty << 2) + i;
        float4 o = make_float4(acc[i][0], acc[i][1], acc[i][2], acc[i][3]);
        *(float4*)(P + ((size_t)(s * 64 + m) * N + n0 + (tx << 2))) = o;
    }
}

// ============ fused attention: dec-fold + scores + softmax + context ========
// grid = 64 (batch), 512 threads
__global__ void attn_step(const float* __restrict__ enc_out,
                          const float* __restrict__ dec_bv,
                          const float* __restrict__ eW,
                          const float* __restrict__ eb)
{
    __shared__ float dec_s[Aa];
    __shared__ float eW_s[Aa];
    __shared__ float sc[224];
    __shared__ float red[512];

    const int b = blockIdx.x, tid = threadIdx.x;

    // fold dec partials + bias
    {
        float v = dec_bv[tid];
#pragma unroll
        for (int s = 0; s < 4; s++) v += g_dec_part[(size_t)(s * 64 + b) * Aa + tid];
        dec_s[tid] = v;
        eW_s[tid] = eW[tid];
    }
    const float eb0 = eb[0];
    __syncthreads();

    // scores: warp per n
    const int wid = tid >> 5, lane = tid & 31;
    for (int n = wid; n < Nn; n += 16) {
        const float* ep = g_enc_proj + ((size_t)b * Nn + n) * Aa;
        float acc = 0.0f;
#pragma unroll 4
        for (int a = lane; a < Aa; a += 32)
            acc += tanh_fast(ep[a] + dec_s[a]) * eW_s[a];
#pragma unroll
        for (int o = 16; o; o >>= 1) acc += __shfl_xor_sync(0xffffffffu, acc, o);
        if (lane == 0) sc[n] = acc + eb0;
    }
    __syncthreads();

    // softmax over 196
    float v = (tid < Nn) ? sc[tid] : -1e30f;
    red[tid] = v; __syncthreads();
    for (int s = 256; s; s >>= 1) { if (tid < s) red[tid] = fmaxf(red[tid], red[tid+s]); __syncthreads(); }
    const float mx = red[0]; __syncthreads();
    float e = (tid < Nn) ? __expf(v - mx) : 0.0f;
    red[tid] = e; __syncthreads();
    for (int s = 256; s; s >>= 1) { if (tid < s) red[tid] += red[tid+s]; __syncthreads(); }
    const float inv = 1.0f / red[0];
    if (tid < Nn) sc[tid] = e * inv;
    __syncthreads();

    // context: thread per h
    const float* eo = enc_out + (size_t)b * Nn * Hh + tid;
    float acc = 0.0f;
#pragma unroll 4
    for (int n = 0; n < Nn; n++) acc += sc[n] * eo[(size_t)n * Hh];
    g_context[b * Hh + tid] = acc;
}

// ============ LSTM cell: fold gate partials + nonlinearity ===================
__global__ void cell_update(int t)
{
    const int b = blockIdx.x, u = threadIdx.x;
    const float* gx = g_gates_x + ((size_t)t * Bb + b) * 4 * Hh;
    float g[4];
#pragma unroll
    for (int gi = 0; gi < 4; gi++) {
        const int col = gi * Hh + u;
        float v = gx[col];
#pragma unroll
        for (int s = 0; s < 4; s++) v += g_gates_part[(size_t)(s * 64 + b) * (4*Hh) + col];
        g[gi] = v;
    }
    const int idx = b * Hh + u;
    const float cn = sigmoid_fast(g[1]) * g_c[idx] + sigmoid_fast(g[0]) * tanh_fast(g[2]);
    const float hn = sigmoid_fast(g[3]) * tanh_fast(cn);
    g_c[idx] = cn;
    g_h[idx] = hn;
    g_hall[(size_t)(t * Bb + b) * Hh + u] = hn;
}

// ============ init / output zero =============================================
__global__ void init_hc()
{
    const int i = blockIdx.x * blockDim.x + threadIdx.x;
    if (i < Bb * Hh) { g_h[i] = 0.0f; g_c[i] = 0.0f; }
}
__global__ void zero_out0(float* __restrict__ out)
{
    for (int i = blockIdx.x * blockDim.x + threadIdx.x; i < Bb * Vv;
         i += gridDim.x * blockDim.x) {
        const int b = i / Vv, v = i - b * Vv;
        out[(size_t)b * Ll * Vv + v] = 0.0f;
    }
}

// ============ launch =========================================================
extern "C" void kernel_launch(void* const* d_in, const int* in_sizes, int n_in,
                              void* d_out, int out_size)
{
    const float* enc_out  = (const float*)d_in[0];
    const int*   captions = (const int*)d_in[1];
    const float* emb      = (const float*)d_in[2];
    const float* W_ih     = (const float*)d_in[3];
    const float* W_hh     = (const float*)d_in[4];
    const float* b_ih     = (const float*)d_in[5];
    const float* b_hh     = (const float*)d_in[6];
    const float* enc_W    = (const float*)d_in[7];
    const float* enc_b    = (const float*)d_in[8];
    const float* dec_W    = (const float*)d_in[9];
    const float* dec_b    = (const float*)d_in[10];
    const float* energy_W = (const float*)d_in[11];
    const float* energy_b = (const float*)d_in[12];
    const float* fc_W     = (const float*)d_in[13];
    const float* fc_b     = (const float*)d_in[14];
    float* out = (float*)d_out;

    float *p_enc_proj, *p_gates_x, *p_hall, *p_ctx, *p_h;
    cudaGetSymbolAddress((void**)&p_enc_proj, g_enc_proj);
    cudaGetSymbolAddress((void**)&p_gates_x,  g_gates_x);
    cudaGetSymbolAddress((void**)&p_hall,     g_hall);
    cudaGetSymbolAddress((void**)&p_ctx,      g_context);
    cudaGetSymbolAddress((void**)&p_h,        g_h);
    float *p_dec_part, *p_gates_part;
    cudaGetSymbolAddress((void**)&p_dec_part,   g_dec_part);
    cudaGetSymbolAddress((void**)&p_gates_part, g_gates_part);

    init_hc<<<(Bb*Hh + 255) / 256, 256>>>();
    zero_out0<<<256, 256>>>(out);

    // enc_proj = encoder_outputs @ enc_W^T + enc_b : [12544, 512] K=512
    gemm128<<<dim3(512/128, 12544/128), 256>>>(enc_out, enc_W, 512, enc_b, nullptr,
                                               p_enc_proj, 12544, 512, 512, nullptr, 0);
    // gates_x[t*64+b] = emb[cap[b,t]] @ W_ih[:, :512]^T + b_ih + b_hh : [1216, 2048]
    gemm128<<<dim3(2048/128, 10), 256>>>(emb, W_ih, 1024, b_ih, b_hh,
                                         p_gates_x, 1216, 2048, 512, captions, 0);

    for (int t = 0; t < Tt; t++) {
        // dec partials: h @ dec_W^T  (K=512 split 4x128)
        gemm64_split<<<dim3(Aa/64, 4), 256>>>(p_h, 512, dec_W, 512, 0,
                                              nullptr, nullptr, 0,
                                              128, p_dec_part, Aa);
        // dec-fold + scores + softmax + context
        attn_step<<<Bb, 512>>>(enc_out, dec_b, energy_W, energy_b);
        // gates partials: [ctx|h] @ [W_ih[:,512:] | W_hh]^T  (K=1024 split 4x256)
        gemm64_split<<<dim3(4*Hh/64, 4), 256>>>(p_ctx, 512, W_ih, 1024, 512,
                                                p_h, W_hh, 512,
                                                256, p_gates_part, 4*Hh);
        // cell
        cell_update<<<Bb, Hh>>>(t);
    }

    // out[b, t+1, :] = hall @ fc_W^T + fc_b : [1216, 20000] K=512
    gemm128<<<dim3((Vv + 127)/128, 10), 256>>>(p_hall, fc_W, 512, fc_b, nullptr,
                                               out, 1216, Vv, 512, nullptr, 1);
}

// round 4
// speedup vs baseline: 1.7432x; 1.4236x over previous
#include <cuda_runtime.h>
#include <cstdint>

#define Bb 64
#define Nn 196
#define Hh 512
#define Aa 512
#define Vv 20000
#define Ll 20
#define Tt 19

// ---------------- scratch ----------------------------------------------------
__device__ float g_enc_proj[Bb*Nn*Aa];        // 25.7 MB
__device__ float g_h[Bb*Hh];
__device__ float g_c[Bb*Hh];
__device__ float g_context[Bb*Hh];
__device__ float g_gates_x[Tt*Bb*4*Hh];
__device__ float g_dec_part[4*Bb*Aa];
__device__ float g_gates_part[4*Bb*4*Hh];
__device__ float g_hall[1280*Hh];

__device__ __forceinline__ float tanh_fast(float x) {
    float y; asm("tanh.approx.f32 %0, %1;" : "=f"(y) : "f"(x)); return y;
}
__device__ __forceinline__ float sigmoid_fast(float x) {
    return 1.0f / (1.0f + __expf(-x));
}
__device__ __forceinline__ unsigned cvt_tf32(float x) {
    unsigned r; asm("cvt.rna.tf32.f32 %0, %1;" : "=r"(r) : "f"(x)); return r;
}
__device__ __forceinline__ void mma_tf32(float c[4], const unsigned a[4], const unsigned b[2]) {
    asm("mma.sync.aligned.m16n8k8.row.col.f32.tf32.tf32.f32 "
        "{%0,%1,%2,%3}, {%4,%5,%6,%7}, {%8,%9}, {%0,%1,%2,%3};"
        : "+f"(c[0]), "+f"(c[1]), "+f"(c[2]), "+f"(c[3])
        : "r"(a[0]), "r"(a[1]), "r"(a[2]), "r"(a[3]), "r"(b[0]), "r"(b[1]));
}

// ============ tensor-core tf32 NT GEMM: C = A @ Bw^T (+bias +bias2) ==========
// 128x128 block tile, BK=16, 256 threads, 8 warps of 64x32 warp tiles.
// caps: A row m gathered as emb[captions[(m%64)*L + m/64]]
// storemode 0: C[m*N+n];  1: out[((m%64)*L + m/64 + 1)*V + n]
__global__ __launch_bounds__(256, 2)
void gemm_tc(const float* __restrict__ A,
             const float* __restrict__ Bw, int ldb,
             const float* __restrict__ bias,
             const float* __restrict__ bias2,
             float* __restrict__ C,
             int Mvalid, int N, int K,
             const int* __restrict__ caps, int storemode)
{
    __shared__ float As[128][17];
    __shared__ float Bs[128][17];

    const int tid  = threadIdx.x;
    const int m0   = blockIdx.y * 128;
    const int n0   = blockIdx.x * 128;
    const int lane = tid & 31;
    const int wid  = tid >> 5;
    const int wm   = (wid & 1) * 64;     // warp M offset in tile
    const int wn   = (wid >> 1) * 32;    // warp N offset in tile
    const int qr   = lane >> 2;          // 0..7
    const int qc   = lane & 3;           // 0..3

    // loaders: row = tid>>1, k-segment = (tid&1)*8
    const int lrow = tid >> 1;
    const int lk   = (tid & 1) << 3;

    const float* arow;
    {
        int am = m0 + lrow;
        if (caps) {
            int mm = (am < Mvalid) ? am : 0;
            int ci = caps[(mm & 63) * Ll + (mm >> 6)];
            ci = ci < 0 ? 0 : (ci >= Vv ? Vv - 1 : ci);
            arow = A + (size_t)ci * K;
        } else {
            int mm = (am < Mvalid) ? am : (Mvalid - 1);
            arow = A + (size_t)mm * K;
        }
    }
    const int bn = n0 + lrow;
    const bool bval = (bn < N);
    const float* brow = Bw + (size_t)(bval ? bn : 0) * ldb;

    float c[2][4][4];   // [mt/2 pairs? no: mt 0..3 compress] -> use [4][4][4] flat below
    // 4 m-tiles x 4 n-tiles x 4 accum
    float acc[4][4][4];
#pragma unroll
    for (int i = 0; i < 4; i++)
#pragma unroll
        for (int j = 0; j < 4; j++)
#pragma unroll
            for (int q = 0; q < 4; q++) acc[i][j][q] = 0.0f;
    (void)c;

    float4 av0 = *(const float4*)(arow + lk);
    float4 av1 = *(const float4*)(arow + lk + 4);
    float4 bv0 = bval ? *(const float4*)(brow + lk)     : make_float4(0.f,0.f,0.f,0.f);
    float4 bv1 = bval ? *(const float4*)(brow + lk + 4) : make_float4(0.f,0.f,0.f,0.f);

    for (int k0 = 0; k0 < K; k0 += 16) {
        As[lrow][lk+0] = av0.x; As[lrow][lk+1] = av0.y; As[lrow][lk+2] = av0.z; As[lrow][lk+3] = av0.w;
        As[lrow][lk+4] = av1.x; As[lrow][lk+5] = av1.y; As[lrow][lk+6] = av1.z; As[lrow][lk+7] = av1.w;
        Bs[lrow][lk+0] = bv0.x; Bs[lrow][lk+1] = bv0.y; Bs[lrow][lk+2] = bv0.z; Bs[lrow][lk+3] = bv0.w;
        Bs[lrow][lk+4] = bv1.x; Bs[lrow][lk+5] = bv1.y; Bs[lrow][lk+6] = bv1.z; Bs[lrow][lk+7] = bv1.w;
        __syncthreads();

        if (k0 + 16 < K) {
            av0 = *(const float4*)(arow + k0 + 16 + lk);
            av1 = *(const float4*)(arow + k0 + 16 + lk + 4);
            bv0 = bval ? *(const float4*)(brow + k0 + 16 + lk)     : make_float4(0.f,0.f,0.f,0.f);
            bv1 = bval ? *(const float4*)(brow + k0 + 16 + lk + 4) : make_float4(0.f,0.f,0.f,0.f);
        }

#pragma unroll
        for (int kk = 0; kk < 16; kk += 8) {
            unsigned af[4][4], bf[4][2];
#pragma unroll
            for (int mt = 0; mt < 4; mt++) {
                const int r = wm + mt * 16 + qr;
                const int k = kk + qc;
                af[mt][0] = cvt_tf32(As[r    ][k    ]);
                af[mt][1] = cvt_tf32(As[r + 8][k    ]);
                af[mt][2] = cvt_tf32(As[r    ][k + 4]);
                af[mt][3] = cvt_tf32(As[r + 8][k + 4]);
            }
#pragma unroll
            for (int nt = 0; nt < 4; nt++) {
                const int n = wn + nt * 8 + qr;
                const int k = kk + qc;
                bf[nt][0] = cvt_tf32(Bs[n][k    ]);
                bf[nt][1] = cvt_tf32(Bs[n][k + 4]);
            }
#pragma unroll
            for (int mt = 0; mt < 4; mt++)
#pragma unroll
                for (int nt = 0; nt < 4; nt++)
                    mma_tf32(acc[mt][nt], af[mt], bf[nt]);
        }
        __syncthreads();
    }

    // epilogue
#pragma unroll
    for (int mt = 0; mt < 4; mt++) {
#pragma unroll
        for (int nt = 0; nt < 4; nt++) {
#pragma unroll
            for (int half = 0; half < 2; half++) {
                const int m = m0 + wm + mt * 16 + qr + half * 8;
                if (m >= Mvalid) continue;
                const int col = n0 + wn + nt * 8 + 2 * qc;
#pragma unroll
                for (int q = 0; q < 2; q++) {
                    const int n = col + q;
                    if (n >= N) continue;
                    float v = acc[mt][nt][half * 2 + q];
                    if (bias)  v += bias[n];
                    if (bias2) v += bias2[n];
                    if (storemode == 0) {
                        C[(size_t)m * N + n] = v;
                    } else {
                        const int t = m >> 6, b = m & 63;
                        C[((size_t)b * Ll + t + 1) * Vv + n] = v;
                    }
                }
            }
        }
    }
}

// ============ small-M (64) split-K GEMM -> partials =========================
__global__ void gemm64_split(const float* __restrict__ A1, int K1,
                             const float* __restrict__ W1, int ldw1, int offw1,
                             const float* __restrict__ A2,
                             const float* __restrict__ W2, int ldw2,
                             int KC, float* __restrict__ P, int N)
{
    __shared__ float As[16][64];
    __shared__ float Ws[16][64];
    const int tid = threadIdx.x;
    const int n0 = blockIdx.x * 64;
    const int s  = blockIdx.y;
    const int kbeg = s * KC, kend = kbeg + KC;

    const int row = tid >> 2;
    const int kc  = (tid & 3) << 2;
    const int tx = tid & 15, ty = tid >> 4;

    float acc[4][4];
#pragma unroll
    for (int i = 0; i < 4; i++)
#pragma unroll
        for (int j = 0; j < 4; j++) acc[i][j] = 0.0f;

    for (int k0 = kbeg; k0 < kend; k0 += 16) {
        float4 av, wv;
        if (k0 < K1) {
            av = *(const float4*)(A1 + (size_t)row * K1 + k0 + kc);
            wv = *(const float4*)(W1 + (size_t)(n0 + row) * ldw1 + offw1 + k0 + kc);
        } else {
            const int kq = k0 - K1;
            av = *(const float4*)(A2 + (size_t)row * 512 + kq + kc);
            wv = *(const float4*)(W2 + (size_t)(n0 + row) * ldw2 + kq + kc);
        }
        As[kc+0][row] = av.x; As[kc+1][row] = av.y; As[kc+2][row] = av.z; As[kc+3][row] = av.w;
        Ws[kc+0][row] = wv.x; Ws[kc+1][row] = wv.y; Ws[kc+2][row] = wv.z; Ws[kc+3][row] = wv.w;
        __syncthreads();
#pragma unroll
        for (int kk = 0; kk < 16; kk++) {
            float4 a4 = *(const float4*)&As[kk][ty << 2];
            float4 w4 = *(const float4*)&Ws[kk][tx << 2];
            float a_[4] = {a4.x, a4.y, a4.z, a4.w};
            float w_[4] = {w4.x, w4.y, w4.z, w4.w};
#pragma unroll
            for (int i = 0; i < 4; i++)
#pragma unroll
                for (int j = 0; j < 4; j++) acc[i][j] += a_[i] * w_[j];
        }
        __syncthreads();
    }

#pragma unroll
    for (int i = 0; i < 4; i++) {
        const int m = (ty << 2) + i;
        float4 o = make_float4(acc[i][0], acc[i][1], acc[i][2], acc[i][3]);
        *(float4*)(P + ((size_t)(s * 64 + m) * N + n0 + (tx << 2))) = o;
    }
}

// ============ fused attention ===============================================
__global__ void attn_step(const float* __restrict__ enc_out,
                          const float* __restrict__ dec_bv,
                          const float* __restrict__ eW,
                          const float* __restrict__ eb)
{
    __shared__ float dec_s[Aa];
    __shared__ float eW_s[Aa];
    __shared__ float sc[224];
    __shared__ float red[512];

    const int b = blockIdx.x, tid = threadIdx.x;

    {
        float v = dec_bv[tid];
#pragma unroll
        for (int s = 0; s < 4; s++) v += g_dec_part[(size_t)(s * 64 + b) * Aa + tid];
        dec_s[tid] = v;
        eW_s[tid] = eW[tid];
    }
    const float eb0 = eb[0];
    __syncthreads();

    const int wid = tid >> 5, lane = tid & 31;
    for (int n = wid; n < Nn; n += 16) {
        const float* ep = g_enc_proj + ((size_t)b * Nn + n) * Aa;
        float acc = 0.0f;
#pragma unroll 4
        for (int a = lane; a < Aa; a += 32)
            acc += tanh_fast(ep[a] + dec_s[a]) * eW_s[a];
#pragma unroll
        for (int o = 16; o; o >>= 1) acc += __shfl_xor_sync(0xffffffffu, acc, o);
        if (lane == 0) sc[n] = acc + eb0;
    }
    __syncthreads();

    float v = (tid < Nn) ? sc[tid] : -1e30f;
    red[tid] = v; __syncthreads();
    for (int s = 256; s; s >>= 1) { if (tid < s) red[tid] = fmaxf(red[tid], red[tid+s]); __syncthreads(); }
    const float mx = red[0]; __syncthreads();
    float e = (tid < Nn) ? __expf(v - mx) : 0.0f;
    red[tid] = e; __syncthreads();
    for (int s = 256; s; s >>= 1) { if (tid < s) red[tid] += red[tid+s]; __syncthreads(); }
    const float inv = 1.0f / red[0];
    if (tid < Nn) sc[tid] = e * inv;
    __syncthreads();

    const float* eo = enc_out + (size_t)b * Nn * Hh + tid;
    float acc = 0.0f;
#pragma unroll 4
    for (int n = 0; n < Nn; n++) acc += sc[n] * eo[(size_t)n * Hh];
    g_context[b * Hh + tid] = acc;
}

// ============ LSTM cell ======================================================
__global__ void cell_update(int t)
{
    const int b = blockIdx.x, u = threadIdx.x;
    const float* gx = g_gates_x + ((size_t)t * Bb + b) * 4 * Hh;
    float g[4];
#pragma unroll
    for (int gi = 0; gi < 4; gi++) {
        const int col = gi * Hh + u;
        float v = gx[col];
#pragma unroll
        for (int s = 0; s < 4; s++) v += g_gates_part[(size_t)(s * 64 + b) * (4*Hh) + col];
        g[gi] = v;
    }
    const int idx = b * Hh + u;
    const float cn = sigmoid_fast(g[1]) * g_c[idx] + sigmoid_fast(g[0]) * tanh_fast(g[2]);
    const float hn = sigmoid_fast(g[3]) * tanh_fast(cn);
    g_c[idx] = cn;
    g_h[idx] = hn;
    g_hall[(size_t)(t * Bb + b) * Hh + u] = hn;
}

// ============ init / zero ====================================================
__global__ void init_hc()
{
    const int i = blockIdx.x * blockDim.x + threadIdx.x;
    if (i < Bb * Hh) { g_h[i] = 0.0f; g_c[i] = 0.0f; }
}
__global__ void zero_out0(float* __restrict__ out)
{
    for (int i = blockIdx.x * blockDim.x + threadIdx.x; i < Bb * Vv;
         i += gridDim.x * blockDim.x) {
        const int b = i / Vv, v = i - b * Vv;
        out[(size_t)b * Ll * Vv + v] = 0.0f;
    }
}

// ============ launch =========================================================
extern "C" void kernel_launch(void* const* d_in, const int* in_sizes, int n_in,
                              void* d_out, int out_size)
{
    const float* enc_out  = (const float*)d_in[0];
    const int*   captions = (const int*)d_in[1];
    const float* emb      = (const float*)d_in[2];
    const float* W_ih     = (const float*)d_in[3];
    const float* W_hh     = (const float*)d_in[4];
    const float* b_ih     = (const float*)d_in[5];
    const float* b_hh     = (const float*)d_in[6];
    const float* enc_W    = (const float*)d_in[7];
    const float* enc_b    = (const float*)d_in[8];
    const float* dec_W    = (const float*)d_in[9];
    const float* dec_b    = (const float*)d_in[10];
    const float* energy_W = (const float*)d_in[11];
    const float* energy_b = (const float*)d_in[12];
    const float* fc_W     = (const float*)d_in[13];
    const float* fc_b     = (const float*)d_in[14];
    float* out = (float*)d_out;

    float *p_enc_proj, *p_gates_x, *p_hall, *p_ctx, *p_h;
    cudaGetSymbolAddress((void**)&p_enc_proj, g_enc_proj);
    cudaGetSymbolAddress((void**)&p_gates_x,  g_gates_x);
    cudaGetSymbolAddress((void**)&p_hall,     g_hall);
    cudaGetSymbolAddress((void**)&p_ctx,      g_context);
    cudaGetSymbolAddress((void**)&p_h,        g_h);
    float *p_dec_part, *p_gates_part;
    cudaGetSymbolAddress((void**)&p_dec_part,   g_dec_part);
    cudaGetSymbolAddress((void**)&p_gates_part, g_gates_part);

    init_hc<<<(Bb*Hh + 255) / 256, 256>>>();
    zero_out0<<<256, 256>>>(out);

    // enc_proj : [12544, 512] K=512
    gemm_tc<<<dim3(512/128, 12544/128), 256>>>(enc_out, enc_W, 512, enc_b, nullptr,
                                               p_enc_proj, 12544, 512, 512, nullptr, 0);
    // gates_x : [1216, 2048] K=512 (embedding gather)
    gemm_tc<<<dim3(2048/128, 10), 256>>>(emb, W_ih, 1024, b_ih, b_hh,
                                         p_gates_x, 1216, 2048, 512, captions, 0);

    for (int t = 0; t < Tt; t++) {
        gemm64_split<<<dim3(Aa/64, 4), 256>>>(p_h, 512, dec_W, 512, 0,
                                              nullptr, nullptr, 0,
                                              128, p_dec_part, Aa);
        attn_step<<<Bb, 512>>>(enc_out, dec_b, energy_W, energy_b);
        gemm64_split<<<dim3(4*Hh/64, 4), 256>>>(p_ctx, 512, W_ih, 1024, 512,
                                                p_h, W_hh, 512,
                                                256, p_gates_part, 4*Hh);
        cell_update<<<Bb, Hh>>>(t);
    }

    // fc : [1216, 20000] K=512
    gemm_tc<<<dim3((Vv + 127)/128, 10), 256>>>(p_hall, fc_W, 512, fc_b, nullptr,
                                               out, 1216, Vv, 512, nullptr, 1);
}

// round 5
// speedup vs baseline: 1.8302x; 1.0500x over previous
#include <cuda_runtime.h>
#include <cstdint>

#define Bb 64
#define Nn 196
#define Hh 512
#define Aa 512
#define Vv 20000
#define Ll 20
#define Tt 19

// ---------------- scratch ----------------------------------------------------
__device__ float g_enc_proj[Bb*Nn*Aa];        // 25.7 MB
__device__ float g_h[Bb*Hh];
__device__ float g_c[Bb*Hh];
__device__ float g_context[Bb*Hh];
__device__ float g_gates_x[Tt*Bb*4*Hh];
__device__ float g_dec_part[4*Bb*Aa];
__device__ float g_gates_part[4*Bb*4*Hh];
__device__ float g_hall[1280*Hh];

__device__ __forceinline__ float tanh_fast(float x) {
    float y; asm("tanh.approx.f32 %0, %1;" : "=f"(y) : "f"(x)); return y;
}
__device__ __forceinline__ float sigmoid_fast(float x) {
    return 1.0f / (1.0f + __expf(-x));
}
__device__ __forceinline__ unsigned cvt_tf32(float x) {
    unsigned r; asm("cvt.rna.tf32.f32 %0, %1;" : "=r"(r) : "f"(x)); return r;
}
__device__ __forceinline__ void mma_tf32(float c[4],
                                         unsigned a0, unsigned a1, unsigned a2, unsigned a3,
                                         unsigned b0, unsigned b1) {
    asm("mma.sync.aligned.m16n8k8.row.col.f32.tf32.tf32.f32 "
        "{%0,%1,%2,%3}, {%4,%5,%6,%7}, {%8,%9}, {%0,%1,%2,%3};"
        : "+f"(c[0]), "+f"(c[1]), "+f"(c[2]), "+f"(c[3])
        : "r"(a0), "r"(a1), "r"(a2), "r"(a3), "r"(b0), "r"(b1));
}

// ============ tensor-core tf32 NT GEMM: C = A @ Bw^T (+bias +bias2) ==========
// 128x128 block tile, BK=16, 256 threads, 8 warps of 64x32 warp tiles.
// Fragment-major SMEM: index = k8*1024 + row*8 + qc*2 + regK  (tf32-converted).
// caps: A row m gathered as emb[captions[(m%64)*L + m/64]]
// storemode 0: C[m*N+n];  1: out[((m%64)*L + m/64 + 1)*V + n]
__global__ __launch_bounds__(256, 2)
void gemm_tc(const float* __restrict__ A,
             const float* __restrict__ Bw, int ldb,
             const float* __restrict__ bias,
             const float* __restrict__ bias2,
             float* __restrict__ C,
             int Mvalid, int N, int K,
             const int* __restrict__ caps, int storemode)
{
    __shared__ unsigned sA[2][2048];   // [stage][k8*1024 + row*8 + qc*2 + regK]
    __shared__ unsigned sB[2][2048];

    const int tid  = threadIdx.x;
    const int m0   = blockIdx.y * 128;
    const int n0   = blockIdx.x * 128;
    const int lane = tid & 31;
    const int wid  = tid >> 5;
    const int wm   = (wid & 1) * 64;
    const int wn   = (wid >> 1) * 32;
    const int qr   = lane >> 2;          // 0..7
    const int qc   = lane & 3;           // 0..3

    // loaders: row = tid>>1, k-segment = (tid&1)*8
    const int lrow = tid >> 1;
    const int lk   = (tid & 1) << 3;
    const int lk8  = lk >> 3;                       // 0 or 1
    const int sbase = lk8 * 1024 + lrow * 8;        // store base (word units)

    const float* arow;
    {
        int am = m0 + lrow;
        if (caps) {
            int mm = (am < Mvalid) ? am : 0;
            int ci = caps[(mm & 63) * Ll + (mm >> 6)];
            ci = ci < 0 ? 0 : (ci >= Vv ? Vv - 1 : ci);
            arow = A + (size_t)ci * K;
        } else {
            int mm = (am < Mvalid) ? am : (Mvalid - 1);
            arow = A + (size_t)mm * K;
        }
    }
    const int bn = n0 + lrow;
    const bool bval = (bn < N);
    const float* brow = Bw + (size_t)(bval ? bn : 0) * ldb;

    float acc[4][4][4];
#pragma unroll
    for (int i = 0; i < 4; i++)
#pragma unroll
        for (int j = 0; j < 4; j++)
#pragma unroll
            for (int q = 0; q < 4; q++) acc[i][j][q] = 0.0f;

    // ---- helpers to fetch + convert + permuted-store one BK tile ----
    float4 av0, av1, bv0, bv1;
    auto fetch = [&](int k0) {
        av0 = *(const float4*)(arow + k0 + lk);
        av1 = *(const float4*)(arow + k0 + lk + 4);
        bv0 = bval ? *(const float4*)(brow + k0 + lk)     : make_float4(0.f,0.f,0.f,0.f);
        bv1 = bval ? *(const float4*)(brow + k0 + lk + 4) : make_float4(0.f,0.f,0.f,0.f);
    };
    auto store_stage = [&](int s) {
        // slots: j -> qc*2+regK : {0,2,4,6,1,3,5,7}; pack as {v0,v4,v1,v5},{v2,v6,v3,v7}
        uint4 p0, p1;
        p0.x = cvt_tf32(av0.x); p0.y = cvt_tf32(av1.x); p0.z = cvt_tf32(av0.y); p0.w = cvt_tf32(av1.y);
        p1.x = cvt_tf32(av0.z); p1.y = cvt_tf32(av1.z); p1.z = cvt_tf32(av0.w); p1.w = cvt_tf32(av1.w);
        *(uint4*)&sA[s][sbase]     = p0;
        *(uint4*)&sA[s][sbase + 4] = p1;
        p0.x = cvt_tf32(bv0.x); p0.y = cvt_tf32(bv1.x); p0.z = cvt_tf32(bv0.y); p0.w = cvt_tf32(bv1.y);
        p1.x = cvt_tf32(bv0.z); p1.y = cvt_tf32(bv1.z); p1.z = cvt_tf32(bv0.w); p1.w = cvt_tf32(bv1.w);
        *(uint4*)&sB[s][sbase]     = p0;
        *(uint4*)&sB[s][sbase + 4] = p1;
    };

    fetch(0);
    store_stage(0);
    __syncthreads();

    const int steps = K >> 4;
    for (int it = 0; it < steps; it++) {
        const int s = it & 1;
        if (it + 1 < steps) fetch((it + 1) << 4);

#pragma unroll
        for (int k8 = 0; k8 < 2; k8++) {
            const unsigned* baseA = &sA[s][k8 * 1024 + qc * 2];
            const unsigned* baseB = &sB[s][k8 * 1024 + qc * 2];
            uint2 afl[4], afh[4], bf[4];
#pragma unroll
            for (int mt = 0; mt < 4; mt++) {
                const int r = wm + mt * 16 + qr;
                afl[mt] = *(const uint2*)&baseA[r * 8];        // a0, a2
                afh[mt] = *(const uint2*)&baseA[(r + 8) * 8];  // a1, a3
            }
#pragma unroll
            for (int nt = 0; nt < 4; nt++) {
                const int n = wn + nt * 8 + qr;
                bf[nt] = *(const uint2*)&baseB[n * 8];         // b0, b1
            }
#pragma unroll
            for (int mt = 0; mt < 4; mt++)
#pragma unroll
                for (int nt = 0; nt < 4; nt++)
                    mma_tf32(acc[mt][nt],
                             afl[mt].x, afh[mt].x, afl[mt].y, afh[mt].y,
                             bf[nt].x, bf[nt].y);
        }

        if (it + 1 < steps) store_stage(s ^ 1);
        __syncthreads();
    }

    // epilogue
#pragma unroll
    for (int mt = 0; mt < 4; mt++) {
#pragma unroll
        for (int nt = 0; nt < 4; nt++) {
#pragma unroll
            for (int half = 0; half < 2; half++) {
                const int m = m0 + wm + mt * 16 + qr + half * 8;
                if (m >= Mvalid) continue;
                const int col = n0 + wn + nt * 8 + 2 * qc;
#pragma unroll
                for (int q = 0; q < 2; q++) {
                    const int n = col + q;
                    if (n >= N) continue;
                    float v = acc[mt][nt][half * 2 + q];
                    if (bias)  v += bias[n];
                    if (bias2) v += bias2[n];
                    if (storemode == 0) {
                        C[(size_t)m * N + n] = v;
                    } else {
                        const int t = m >> 6, b = m & 63;
                        C[((size_t)b * Ll + t + 1) * Vv + n] = v;
                    }
                }
            }
        }
    }
}

// ============ small-M (64) split-K GEMM -> partials =========================
__global__ void gemm64_split(const float* __restrict__ A1, int K1,
                             const float* __restrict__ W1, int ldw1, int offw1,
                             const float* __restrict__ A2,
                             const float* __restrict__ W2, int ldw2,
                             int KC, float* __restrict__ P, int N)
{
    __shared__ float As[16][64];
    __shared__ float Ws[16][64];
    const int tid = threadIdx.x;
    const int n0 = blockIdx.x * 64;
    const int s  = blockIdx.y;
    const int kbeg = s * KC, kend = kbeg + KC;

    const int row = tid >> 2;
    const int kc  = (tid & 3) << 2;
    const int tx = tid & 15, ty = tid >> 4;

    float acc[4][4];
#pragma unroll
    for (int i = 0; i < 4; i++)
#pragma unroll
        for (int j = 0; j < 4; j++) acc[i][j] = 0.0f;

    for (int k0 = kbeg; k0 < kend; k0 += 16) {
        float4 av, wv;
        if (k0 < K1) {
            av = *(const float4*)(A1 + (size_t)row * K1 + k0 + kc);
            wv = *(const float4*)(W1 + (size_t)(n0 + row) * ldw1 + offw1 + k0 + kc);
        } else {
            const int kq = k0 - K1;
            av = *(const float4*)(A2 + (size_t)row * 512 + kq + kc);
            wv = *(const float4*)(W2 + (size_t)(n0 + row) * ldw2 + kq + kc);
        }
        As[kc+0][row] = av.x; As[kc+1][row] = av.y; As[kc+2][row] = av.z; As[kc+3][row] = av.w;
        Ws[kc+0][row] = wv.x; Ws[kc+1][row] = wv.y; Ws[kc+2][row] = wv.z; Ws[kc+3][row] = wv.w;
        __syncthreads();
#pragma unroll
        for (int kk = 0; kk < 16; kk++) {
            float4 a4 = *(const float4*)&As[kk][ty << 2];
            float4 w4 = *(const float4*)&Ws[kk][tx << 2];
            float a_[4] = {a4.x, a4.y, a4.z, a4.w};
            float w_[4] = {w4.x, w4.y, w4.z, w4.w};
#pragma unroll
            for (int i = 0; i < 4; i++)
#pragma unroll
                for (int j = 0; j < 4; j++) acc[i][j] += a_[i] * w_[j];
        }
        __syncthreads();
    }

#pragma unroll
    for (int i = 0; i < 4; i++) {
        const int m = (ty << 2) + i;
        float4 o = make_float4(acc[i][0], acc[i][1], acc[i][2], acc[i][3]);
        *(float4*)(P + ((size_t)(s * 64 + m) * N + n0 + (tx << 2))) = o;
    }
}

// ============ fused attention ===============================================
__global__ void attn_step(const float* __restrict__ enc_out,
                          const float* __restrict__ dec_bv,
                          const float* __restrict__ eW,
                          const float* __restrict__ eb)
{
    __shared__ float dec_s[Aa];
    __shared__ float eW_s[Aa];
    __shared__ float sc[224];
    __shared__ float red[512];

    const int b = blockIdx.x, tid = threadIdx.x;

    {
        float v = dec_bv[tid];
#pragma unroll
        for (int s = 0; s < 4; s++) v += g_dec_part[(size_t)(s * 64 + b) * Aa + tid];
        dec_s[tid] = v;
        eW_s[tid] = eW[tid];
    }
    const float eb0 = eb[0];
    __syncthreads();

    const int wid = tid >> 5, lane = tid & 31;
    for (int n = wid; n < Nn; n += 16) {
        const float* ep = g_enc_proj + ((size_t)b * Nn + n) * Aa;
        float acc = 0.0f;
#pragma unroll 4
        for (int a = lane; a < Aa; a += 32)
            acc += tanh_fast(ep[a] + dec_s[a]) * eW_s[a];
#pragma unroll
        for (int o = 16; o; o >>= 1) acc += __shfl_xor_sync(0xffffffffu, acc, o);
        if (lane == 0) sc[n] = acc + eb0;
    }
    __syncthreads();

    float v = (tid < Nn) ? sc[tid] : -1e30f;
    red[tid] = v; __syncthreads();
    for (int s = 256; s; s >>= 1) { if (tid < s) red[tid] = fmaxf(red[tid], red[tid+s]); __syncthreads(); }
    const float mx = red[0]; __syncthreads();
    float e = (tid < Nn) ? __expf(v - mx) : 0.0f;
    red[tid] = e; __syncthreads();
    for (int s = 256; s; s >>= 1) { if (tid < s) red[tid] += red[tid+s]; __syncthreads(); }
    const float inv = 1.0f / red[0];
    if (tid < Nn) sc[tid] = e * inv;
    __syncthreads();

    const float* eo = enc_out + (size_t)b * Nn * Hh + tid;
    float acc = 0.0f;
#pragma unroll 4
    for (int n = 0; n < Nn; n++) acc += sc[n] * eo[(size_t)n * Hh];
    g_context[b * Hh + tid] = acc;
}

// ============ LSTM cell ======================================================
__global__ void cell_update(int t)
{
    const int b = blockIdx.x, u = threadIdx.x;
    const float* gx = g_gates_x + ((size_t)t * Bb + b) * 4 * Hh;
    float g[4];
#pragma unroll
    for (int gi = 0; gi < 4; gi++) {
        const int col = gi * Hh + u;
        float v = gx[col];
#pragma unroll
        for (int s = 0; s < 4; s++) v += g_gates_part[(size_t)(s * 64 + b) * (4*Hh) + col];
        g[gi] = v;
    }
    const int idx = b * Hh + u;
    const float cn = sigmoid_fast(g[1]) * g_c[idx] + sigmoid_fast(g[0]) * tanh_fast(g[2]);
    const float hn = sigmoid_fast(g[3]) * tanh_fast(cn);
    g_c[idx] = cn;
    g_h[idx] = hn;
    g_hall[(size_t)(t * Bb + b) * Hh + u] = hn;
}

// ============ init / zero ====================================================
__global__ void init_hc()
{
    const int i = blockIdx.x * blockDim.x + threadIdx.x;
    if (i < Bb * Hh) { g_h[i] = 0.0f; g_c[i] = 0.0f; }
}
__global__ void zero_out0(float* __restrict__ out)
{
    for (int i = blockIdx.x * blockDim.x + threadIdx.x; i < Bb * Vv;
         i += gridDim.x * blockDim.x) {
        const int b = i / Vv, v = i - b * Vv;
        out[(size_t)b * Ll * Vv + v] = 0.0f;
    }
}

// ============ launch =========================================================
extern "C" void kernel_launch(void* const* d_in, const int* in_sizes, int n_in,
                              void* d_out, int out_size)
{
    const float* enc_out  = (const float*)d_in[0];
    const int*   captions = (const int*)d_in[1];
    const float* emb      = (const float*)d_in[2];
    const float* W_ih     = (const float*)d_in[3];
    const float* W_hh     = (const float*)d_in[4];
    const float* b_ih     = (const float*)d_in[5];
    const float* b_hh     = (const float*)d_in[6];
    const float* enc_W    = (const float*)d_in[7];
    const float* enc_b    = (const float*)d_in[8];
    const float* dec_W    = (const float*)d_in[9];
    const float* dec_b    = (const float*)d_in[10];
    const float* energy_W = (const float*)d_in[11];
    const float* energy_b = (const float*)d_in[12];
    const float* fc_W     = (const float*)d_in[13];
    const float* fc_b     = (const float*)d_in[14];
    float* out = (float*)d_out;

    float *p_enc_proj, *p_gates_x, *p_hall, *p_ctx, *p_h;
    cudaGetSymbolAddress((void**)&p_enc_proj, g_enc_proj);
    cudaGetSymbolAddress((void**)&p_gates_x,  g_gates_x);
    cudaGetSymbolAddress((void**)&p_hall,     g_hall);
    cudaGetSymbolAddress((void**)&p_ctx,      g_context);
    cudaGetSymbolAddress((void**)&p_h,        g_h);
    float *p_dec_part, *p_gates_part;
    cudaGetSymbolAddress((void**)&p_dec_part,   g_dec_part);
    cudaGetSymbolAddress((void**)&p_gates_part, g_gates_part);

    init_hc<<<(Bb*Hh + 255) / 256, 256>>>();
    zero_out0<<<256, 256>>>(out);

    // enc_proj : [12544, 512] K=512
    gemm_tc<<<dim3(512/128, 12544/128), 256>>>(enc_out, enc_W, 512, enc_b, nullptr,
                                               p_enc_proj, 12544, 512, 512, nullptr, 0);
    // gates_x : [1216, 2048] K=512 (embedding gather)
    gemm_tc<<<dim3(2048/128, 10), 256>>>(emb, W_ih, 1024, b_ih, b_hh,
                                         p_gates_x, 1216, 2048, 512, captions, 0);

    for (int t = 0; t < Tt; t++) {
        gemm64_split<<<dim3(Aa/64, 4), 256>>>(p_h, 512, dec_W, 512, 0,
                                              nullptr, nullptr, 0,
                                              128, p_dec_part, Aa);
        attn_step<<<Bb, 512>>>(enc_out, dec_b, energy_W, energy_b);
        gemm64_split<<<dim3(4*Hh/64, 4), 256>>>(p_ctx, 512, W_ih, 1024, 512,
                                                p_h, W_hh, 512,
                                                256, p_gates_part, 4*Hh);
        cell_update<<<Bb, Hh>>>(t);
    }

    // fc : [1216, 20000] K=512
    gemm_tc<<<dim3((Vv + 127)/128, 10), 256>>>(p_hall, fc_W, 512, fc_b, nullptr,
                                               out, 1216, Vv, 512, nullptr, 1);
}